// round 11
// baseline (speedup 1.0000x reference)
#include <cuda_runtime.h>
#include <math.h>
#include <stdint.h>

// Problem constants
#define BATCH 8
#define SEQ   1024
#define EMB   768
#define NHEAD 12
#define HD    64
#define M_ROWS (BATCH * SEQ)        // 8192
#define QKV_N  (3 * EMB)            // 2304

// Scratch (device globals — no allocations allowed)
__device__ float g_Q[BATCH * NHEAD * SEQ * HD];   // [b,h,t,d] fp32
__device__ float g_K[BATCH * NHEAD * SEQ * HD];
__device__ float g_V[BATCH * NHEAD * SEQ * HD];
__device__ float g_Y[M_ROWS * EMB];               // attention out (tf32-rounded)
__device__ float g_Xc[M_ROWS * EMB];              // x, tf32-rounded
__device__ float g_Wa[EMB * QKV_N];               // W_attn, tf32-rounded
__device__ float g_Wp[EMB * EMB];                 // W_proj, tf32-rounded

// ---------------------------------------------------------------------------
// helpers
// ---------------------------------------------------------------------------
__device__ __forceinline__ uint32_t f2tf32(float f) {
    uint32_t u;
    asm("cvt.rna.tf32.f32 %0, %1;" : "=r"(u) : "f"(f));
    return u;
}
__device__ __forceinline__ float f2tf32f(float f) {
    return __uint_as_float(f2tf32(f));
}

__device__ __forceinline__ void mma_tf32(float c[4],
                                         uint32_t a0, uint32_t a1, uint32_t a2, uint32_t a3,
                                         uint32_t b0, uint32_t b1) {
    asm volatile(
        "mma.sync.aligned.m16n8k8.row.col.f32.tf32.tf32.f32 "
        "{%0,%1,%2,%3}, {%4,%5,%6,%7}, {%8,%9}, {%0,%1,%2,%3};\n"
        : "+f"(c[0]), "+f"(c[1]), "+f"(c[2]), "+f"(c[3])
        : "r"(a0), "r"(a1), "r"(a2), "r"(a3), "r"(b0), "r"(b1));
}

// ---------------------------------------------------------------------------
// Pre-pass: element-wise tf32 rounding. Destination global chosen INSIDE the
// kernel (never pass a __device__ symbol from host).
// ---------------------------------------------------------------------------
template<int WHICH>   // 0 -> g_Xc, 1 -> g_Wa, 2 -> g_Wp
__global__ __launch_bounds__(256) void cvt_tf32_kernel(
    const float* __restrict__ in, int n4)
{
    float* __restrict__ out = (WHICH == 0) ? g_Xc : (WHICH == 1) ? g_Wa : g_Wp;
    const int i = blockIdx.x * 256 + threadIdx.x;
    if (i < n4) {
        float4 v = ((const float4*)in)[i];
        v.x = f2tf32f(v.x); v.y = f2tf32f(v.y);
        v.z = f2tf32f(v.z); v.w = f2tf32f(v.w);
        ((float4*)out)[i] = v;
    }
}

// ---------------------------------------------------------------------------
// Double-buffered tf32 GEMM, CTA tile 256(M) x 128(N), BK=16.
// 8 warps as 4(wm) x 2(wn); warp tile 64x64 (mi=0..3) -> B-frags reused 4x,
// smem read traffic per output area drops 64KB -> 44KB per ktile.
// Dynamic smem: As[2][16][APAD=264], Bs[2][16][BPAD=136].
// MODE 0: QKV — scatter into g_Q/g_K/g_V. MODE 1: proj — g_Y -> out.
// ---------------------------------------------------------------------------
#define GBK 16
#define APAD 264   // m-dim 256 + 8: conflict-free a-frag loads (tig*8 + gid)
#define BPAD 136   // n-dim 128 + 8: conflict-free b-frag loads
#define KTILES 48
#define GEMM_SMEM ((2 * GBK * APAD + 2 * GBK * BPAD) * 4)   // 51200 bytes

template<int NDIM, int MODE>
__global__ __launch_bounds__(256, 1) void gemm_db_kernel(
    const float* __restrict__ bias, float* __restrict__ out)
{
    extern __shared__ float smf[];
    float* As = smf;                        // [buf*16 + k][m(264)]
    float* Bs = smf + 2 * GBK * APAD;       // [buf*16 + k][n(136)]

    const float* __restrict__ A = (MODE == 1) ? g_Y : g_Xc;
    const float* __restrict__ B = (MODE == 0) ? g_Wa : g_Wp;

    const int tid = threadIdx.x;
    const int m0 = blockIdx.y * 256;
    const int n0 = blockIdx.x * 128;

    const int wid = tid >> 5;
    const int lane = tid & 31;
    const int wm = wid & 3;            // 4 warps in M (64 rows each)
    const int wn = wid >> 2;           // 2 warps in N (64 cols each)
    const int gid = lane >> 2;
    const int tig = lane & 3;

    float c[4][8][4];
#pragma unroll
    for (int mi = 0; mi < 4; mi++)
#pragma unroll
        for (int ni = 0; ni < 8; ni++)
#pragma unroll
            for (int v = 0; v < 4; v++) c[mi][ni][v] = 0.f;

    float4 aReg[4], bReg[2];

    // staging maps: A: 256 rows x 4 float4 = 1024 chunks, 4/thread
    //               B: 16 rows x 32 float4 = 512 chunks, 2/thread

    // ---- prologue: tile 0 -> buf 0 ----
#pragma unroll
    for (int i = 0; i < 4; i++) {
        const int idx = tid + i * 256;
        aReg[i] = *(const float4*)(A + (size_t)(m0 + (idx >> 2)) * EMB + ((idx & 3) << 2));
    }
#pragma unroll
    for (int i = 0; i < 2; i++) {
        const int idx = tid + i * 256;
        bReg[i] = *(const float4*)(B + (size_t)(idx >> 5) * NDIM + n0 + ((idx & 31) << 2));
    }
#pragma unroll
    for (int i = 0; i < 4; i++) {
        const int idx = tid + i * 256;
        const int ar = idx >> 2, ac = (idx & 3) << 2;
        As[(ac + 0) * APAD + ar] = aReg[i].x;
        As[(ac + 1) * APAD + ar] = aReg[i].y;
        As[(ac + 2) * APAD + ar] = aReg[i].z;
        As[(ac + 3) * APAD + ar] = aReg[i].w;
    }
#pragma unroll
    for (int i = 0; i < 2; i++) {
        const int idx = tid + i * 256;
        const int br = idx >> 5, bc = (idx & 31) << 2;
        *(float4*)&Bs[br * BPAD + bc] = bReg[i];
    }
    __syncthreads();

    for (int t = 0; t < KTILES; t++) {
        const int buf = t & 1;
        const float* Asb = As + buf * GBK * APAD;
        const float* Bsb = Bs + buf * GBK * BPAD;

        // prefetch next tile into registers
        if (t + 1 < KTILES) {
            const int k0 = (t + 1) * GBK;
#pragma unroll
            for (int i = 0; i < 4; i++) {
                const int idx = tid + i * 256;
                aReg[i] = *(const float4*)(A + (size_t)(m0 + (idx >> 2)) * EMB + k0 + ((idx & 3) << 2));
            }
#pragma unroll
            for (int i = 0; i < 2; i++) {
                const int idx = tid + i * 256;
                bReg[i] = *(const float4*)(B + (size_t)(k0 + (idx >> 5)) * NDIM + n0 + ((idx & 31) << 2));
            }
        }

        // compute on current buffer
#pragma unroll
        for (int kt = 0; kt < 2; kt++) {
            const int kk = kt * 8;
            float a[4][4];
#pragma unroll
            for (int mi = 0; mi < 4; mi++) {
                const int mb = wm * 64 + mi * 16;
                a[mi][0] = Asb[(kk + tig) * APAD + mb + gid];
                a[mi][1] = Asb[(kk + tig) * APAD + mb + gid + 8];
                a[mi][2] = Asb[(kk + tig + 4) * APAD + mb + gid];
                a[mi][3] = Asb[(kk + tig + 4) * APAD + mb + gid + 8];
            }
            float b[8][2];
#pragma unroll
            for (int ni = 0; ni < 8; ni++) {
                const int nb = wn * 64 + ni * 8;
                b[ni][0] = Bsb[(kk + tig) * BPAD + nb + gid];
                b[ni][1] = Bsb[(kk + tig + 4) * BPAD + nb + gid];
            }
#pragma unroll
            for (int mi = 0; mi < 4; mi++)
#pragma unroll
                for (int ni = 0; ni < 8; ni++)
                    mma_tf32(c[mi][ni],
                             __float_as_uint(a[mi][0]), __float_as_uint(a[mi][1]),
                             __float_as_uint(a[mi][2]), __float_as_uint(a[mi][3]),
                             __float_as_uint(b[ni][0]), __float_as_uint(b[ni][1]));
        }

        // store prefetched tile into the other buffer
        if (t + 1 < KTILES) {
            float* Asn = As + (buf ^ 1) * GBK * APAD;
            float* Bsn = Bs + (buf ^ 1) * GBK * BPAD;
#pragma unroll
            for (int i = 0; i < 4; i++) {
                const int idx = tid + i * 256;
                const int ar = idx >> 2, ac = (idx & 3) << 2;
                Asn[(ac + 0) * APAD + ar] = aReg[i].x;
                Asn[(ac + 1) * APAD + ar] = aReg[i].y;
                Asn[(ac + 2) * APAD + ar] = aReg[i].z;
                Asn[(ac + 3) * APAD + ar] = aReg[i].w;
            }
#pragma unroll
            for (int i = 0; i < 2; i++) {
                const int idx = tid + i * 256;
                const int br = idx >> 5, bc = (idx & 31) << 2;
                *(float4*)&Bsn[br * BPAD + bc] = bReg[i];
            }
            __syncthreads();
        }
    }

    // epilogue
#pragma unroll
    for (int mi = 0; mi < 4; mi++) {
#pragma unroll
        for (int half = 0; half < 2; half++) {
            const int m = m0 + wm * 64 + mi * 16 + gid + half * 8;
#pragma unroll
            for (int ni = 0; ni < 8; ni++) {
                const int n = n0 + wn * 64 + ni * 8 + 2 * tig;
                const float v0 = c[mi][ni][half * 2 + 0] + bias[n];
                const float v1 = c[mi][ni][half * 2 + 1] + bias[n + 1];
                if (MODE == 0) {
                    const int bb = m >> 10;
                    const int t = m & 1023;
#pragma unroll
                    for (int e = 0; e < 2; e++) {
                        const int nn = n + e;
                        const float vv = e ? v1 : v0;
                        const int which = nn / EMB;
                        const int cc = nn - which * EMB;
                        const int h = cc >> 6;
                        const int d = cc & 63;
                        float* dst = (which == 0) ? g_Q : (which == 1) ? g_K : g_V;
                        dst[(((size_t)bb * NHEAD + h) * SEQ + t) * HD + d] = vv;
                    }
                } else {
                    float2 v2; v2.x = v0; v2.y = v1;
                    *(float2*)(out + (size_t)m * NDIM + n) = v2;
                }
            }
        }
    }
}

// ---------------------------------------------------------------------------
// Tensor-core causal flash attention (tf32 m16n8k8) — unchanged from R10.
// ---------------------------------------------------------------------------
#define ASTR 68

__global__ __launch_bounds__(128) void attn_mma_kernel()
{
    __shared__ uint32_t KVs[64 * ASTR];
    __shared__ uint32_t Ps[64 * ASTR];

    const int bh = blockIdx.y;
    const int q0 = blockIdx.x * 64;
    const int tid = threadIdx.x;
    const int wid = tid >> 5;
    const int lane = tid & 31;
    const int gid = lane >> 2;
    const int tig = lane & 3;
    const int w16 = wid * 16;

    const float* Qbase = g_Q + (size_t)bh * SEQ * HD;
    const float* Kbase = g_K + (size_t)bh * SEQ * HD;
    const float* Vbase = g_V + (size_t)bh * SEQ * HD;

#pragma unroll
    for (int i = 0; i < 8; i++) {
        int idx = tid + i * 128;
        int r = idx >> 4, dq = (idx & 15) << 2;
        float4 v = *(const float4*)(Qbase + (size_t)(q0 + r) * HD + dq);
        uint32_t* dst = &Ps[r * ASTR + dq];
        dst[0] = f2tf32(v.x * 0.125f);
        dst[1] = f2tf32(v.y * 0.125f);
        dst[2] = f2tf32(v.z * 0.125f);
        dst[3] = f2tf32(v.w * 0.125f);
    }
    __syncthreads();

    uint32_t qa[8][4];
#pragma unroll
    for (int kk = 0; kk < 8; kk++) {
        qa[kk][0] = Ps[(w16 + gid) * ASTR + 8 * kk + tig];
        qa[kk][1] = Ps[(w16 + gid + 8) * ASTR + 8 * kk + tig];
        qa[kk][2] = Ps[(w16 + gid) * ASTR + 8 * kk + tig + 4];
        qa[kk][3] = Ps[(w16 + gid + 8) * ASTR + 8 * kk + tig + 4];
    }

    float o[8][4];
#pragma unroll
    for (int ni = 0; ni < 8; ni++)
#pragma unroll
        for (int v = 0; v < 4; v++) o[ni][v] = 0.f;
    float m0 = -1e30f, m1 = -1e30f, l0 = 0.f, l1 = 0.f;

    for (int t0 = 0; t0 <= q0; t0 += 64) {
        __syncthreads();

#pragma unroll
        for (int i = 0; i < 8; i++) {
            int idx = tid + i * 128;
            int r = idx >> 4, dq = (idx & 15) << 2;
            float4 v = *(const float4*)(Kbase + (size_t)(t0 + r) * HD + dq);
            uint32_t* dst = &KVs[r * ASTR + dq];
            dst[0] = f2tf32(v.x); dst[1] = f2tf32(v.y);
            dst[2] = f2tf32(v.z); dst[3] = f2tf32(v.w);
        }
        __syncthreads();

        float4 vreg[8];
#pragma unroll
        for (int i = 0; i < 8; i++) {
            int idx = tid + i * 128;
            vreg[i] = *(const float4*)(Vbase + (size_t)(t0 + (idx >> 4)) * HD + ((idx & 15) << 2));
        }

        float s[8][4];
#pragma unroll
        for (int ni = 0; ni < 8; ni++)
#pragma unroll
            for (int v = 0; v < 4; v++) s[ni][v] = 0.f;

#pragma unroll
        for (int kk = 0; kk < 8; kk++) {
#pragma unroll
            for (int ni = 0; ni < 8; ni++) {
                uint32_t b0 = KVs[(8 * ni + gid) * ASTR + 8 * kk + tig];
                uint32_t b1 = KVs[(8 * ni + gid) * ASTR + 8 * kk + tig + 4];
                mma_tf32(s[ni], qa[kk][0], qa[kk][1], qa[kk][2], qa[kk][3], b0, b1);
            }
        }

        if (t0 == q0) {
            const int r0 = w16 + gid, r1 = r0 + 8;
#pragma unroll
            for (int ni = 0; ni < 8; ni++) {
                const int key0 = 8 * ni + 2 * tig;
                if (key0 > r0)     s[ni][0] = -1e30f;
                if (key0 + 1 > r0) s[ni][1] = -1e30f;
                if (key0 > r1)     s[ni][2] = -1e30f;
                if (key0 + 1 > r1) s[ni][3] = -1e30f;
            }
        }

        float rmax0 = -1e30f, rmax1 = -1e30f;
#pragma unroll
        for (int ni = 0; ni < 8; ni++) {
            rmax0 = fmaxf(rmax0, fmaxf(s[ni][0], s[ni][1]));
            rmax1 = fmaxf(rmax1, fmaxf(s[ni][2], s[ni][3]));
        }
        rmax0 = fmaxf(rmax0, __shfl_xor_sync(0xffffffffu, rmax0, 1));
        rmax0 = fmaxf(rmax0, __shfl_xor_sync(0xffffffffu, rmax0, 2));
        rmax1 = fmaxf(rmax1, __shfl_xor_sync(0xffffffffu, rmax1, 1));
        rmax1 = fmaxf(rmax1, __shfl_xor_sync(0xffffffffu, rmax1, 2));

        const float mn0 = fmaxf(m0, rmax0);
        const float mn1 = fmaxf(m1, rmax1);
        const float cr0 = __expf(m0 - mn0);
        const float cr1 = __expf(m1 - mn1);
        m0 = mn0; m1 = mn1;

        float sum0 = 0.f, sum1 = 0.f;
#pragma unroll
        for (int ni = 0; ni < 8; ni++) {
            s[ni][0] = __expf(s[ni][0] - m0);
            s[ni][1] = __expf(s[ni][1] - m0);
            s[ni][2] = __expf(s[ni][2] - m1);
            s[ni][3] = __expf(s[ni][3] - m1);
            sum0 += s[ni][0] + s[ni][1];
            sum1 += s[ni][2] + s[ni][3];
            o[ni][0] *= cr0; o[ni][1] *= cr0;
            o[ni][2] *= cr1; o[ni][3] *= cr1;
        }
        sum0 += __shfl_xor_sync(0xffffffffu, sum0, 1);
        sum0 += __shfl_xor_sync(0xffffffffu, sum0, 2);
        sum1 += __shfl_xor_sync(0xffffffffu, sum1, 1);
        sum1 += __shfl_xor_sync(0xffffffffu, sum1, 2);
        l0 = l0 * cr0 + sum0;
        l1 = l1 * cr1 + sum1;

        __syncthreads();

#pragma unroll
        for (int i = 0; i < 8; i++) {
            int idx = tid + i * 128;
            int r = idx >> 4, dq = (idx & 15) << 2;
            uint32_t* dst = &KVs[r * ASTR + dq];
            dst[0] = f2tf32(vreg[i].x); dst[1] = f2tf32(vreg[i].y);
            dst[2] = f2tf32(vreg[i].z); dst[3] = f2tf32(vreg[i].w);
        }
#pragma unroll
        for (int ni = 0; ni < 8; ni++) {
            uint32_t* d0 = &Ps[(w16 + gid) * ASTR + 8 * ni + 2 * tig];
            d0[0] = f2tf32(s[ni][0]); d0[1] = f2tf32(s[ni][1]);
            uint32_t* d1 = &Ps[(w16 + gid + 8) * ASTR + 8 * ni + 2 * tig];
            d1[0] = f2tf32(s[ni][2]); d1[1] = f2tf32(s[ni][3]);
        }
        __syncthreads();

#pragma unroll
        for (int kk = 0; kk < 8; kk++) {
            uint32_t pa0 = Ps[(w16 + gid) * ASTR + 8 * kk + tig];
            uint32_t pa1 = Ps[(w16 + gid + 8) * ASTR + 8 * kk + tig];
            uint32_t pa2 = Ps[(w16 + gid) * ASTR + 8 * kk + tig + 4];
            uint32_t pa3 = Ps[(w16 + gid + 8) * ASTR + 8 * kk + tig + 4];
#pragma unroll
            for (int ni = 0; ni < 8; ni++) {
                uint32_t b0 = KVs[(8 * kk + tig) * ASTR + 8 * ni + gid];
                uint32_t b1 = KVs[(8 * kk + tig + 4) * ASTR + 8 * ni + gid];
                mma_tf32(o[ni], pa0, pa1, pa2, pa3, b0, b1);
            }
        }
    }

    // writeback (tf32-rounded so proj GEMM consumes without cvt)
    const float inv0 = 1.f / l0;
    const float inv1 = 1.f / l1;
    const int b = bh / NHEAD;
    const int h = bh - b * NHEAD;
    float* Yb = g_Y + ((size_t)(b * SEQ + q0 + w16 + gid)) * EMB + h * HD;
#pragma unroll
    for (int ni = 0; ni < 8; ni++) {
        float2 v0;
        v0.x = f2tf32f(o[ni][0] * inv0); v0.y = f2tf32f(o[ni][1] * inv0);
        *(float2*)(Yb + 8 * ni + 2 * tig) = v0;
        float2 v1;
        v1.x = f2tf32f(o[ni][2] * inv1); v1.y = f2tf32f(o[ni][3] * inv1);
        *(float2*)(Yb + (size_t)8 * EMB + 8 * ni + 2 * tig) = v1;
    }
}

// ---------------------------------------------------------------------------
extern "C" void kernel_launch(void* const* d_in, const int* in_sizes, int n_in,
                              void* d_out, int out_size)
{
    const float* x      = (const float*)d_in[0];
    const float* W_attn = (const float*)d_in[1];
    const float* b_attn = (const float*)d_in[2];
    const float* W_proj = (const float*)d_in[3];
    const float* b_proj = (const float*)d_in[4];
    float* out = (float*)d_out;

    (void)in_sizes; (void)n_in; (void)out_size;

    cudaFuncSetAttribute((const void*)gemm_db_kernel<QKV_N, 0>,
                         cudaFuncAttributeMaxDynamicSharedMemorySize, GEMM_SMEM);
    cudaFuncSetAttribute((const void*)gemm_db_kernel<EMB, 1>,
                         cudaFuncAttributeMaxDynamicSharedMemorySize, GEMM_SMEM);

    // pre-pass: tf32-round operands (destination globals selected in-kernel)
    cvt_tf32_kernel<0><<<(M_ROWS * EMB / 4 + 255) / 256, 256>>>(x, M_ROWS * EMB / 4);
    cvt_tf32_kernel<1><<<(EMB * QKV_N / 4 + 255) / 256, 256>>>(W_attn, EMB * QKV_N / 4);
    cvt_tf32_kernel<2><<<(EMB * EMB / 4 + 255) / 256, 256>>>(W_proj, EMB * EMB / 4);

    dim3 g1(QKV_N / 128, M_ROWS / 256);    // (18, 32)
    gemm_db_kernel<QKV_N, 0><<<g1, 256, GEMM_SMEM>>>(b_attn, nullptr);

    dim3 g2(SEQ / 64, BATCH * NHEAD);      // (16, 96)
    attn_mma_kernel<<<g2, 128>>>();

    dim3 g3(EMB / 128, M_ROWS / 256);      // (6, 32)
    gemm_db_kernel<EMB, 1><<<g3, 256, GEMM_SMEM>>>(b_proj, out);
}

// round 13
// speedup vs baseline: 1.4349x; 1.4349x over previous
#include <cuda_runtime.h>
#include <cuda_fp16.h>
#include <math.h>
#include <stdint.h>

// Problem constants
#define BATCH 8
#define SEQ   1024
#define EMB   768
#define NHEAD 12
#define HD    64
#define M_ROWS (BATCH * SEQ)        // 8192
#define QKV_N  (3 * EMB)            // 2304

// Scratch (device globals — no allocations allowed)
__device__ float  g_Q[BATCH * NHEAD * SEQ * HD];   // [b,h,t,d] fp32
__device__ float  g_K[BATCH * NHEAD * SEQ * HD];
__device__ float  g_V[BATCH * NHEAD * SEQ * HD];
__device__ __half g_Xh[M_ROWS * EMB];              // x as fp16, [m][k]
__device__ __half g_WaT[QKV_N * EMB];              // W_attn^T fp16, [n][k]
__device__ __half g_WpT[EMB * EMB];                // W_proj^T fp16, [n][k]
__device__ __half g_Yh[M_ROWS * EMB];              // attention out fp16, [m][k]

// ---------------------------------------------------------------------------
// helpers
// ---------------------------------------------------------------------------
__device__ __forceinline__ uint32_t f2tf32(float f) {
    uint32_t u;
    asm("cvt.rna.tf32.f32 %0, %1;" : "=r"(u) : "f"(f));
    return u;
}

__device__ __forceinline__ void mma_tf32(float c[4],
                                         uint32_t a0, uint32_t a1, uint32_t a2, uint32_t a3,
                                         uint32_t b0, uint32_t b1) {
    asm volatile(
        "mma.sync.aligned.m16n8k8.row.col.f32.tf32.tf32.f32 "
        "{%0,%1,%2,%3}, {%4,%5,%6,%7}, {%8,%9}, {%0,%1,%2,%3};\n"
        : "+f"(c[0]), "+f"(c[1]), "+f"(c[2]), "+f"(c[3])
        : "r"(a0), "r"(a1), "r"(a2), "r"(a3), "r"(b0), "r"(b1));
}

__device__ __forceinline__ void mma_f16(float c[4],
                                        uint32_t a0, uint32_t a1, uint32_t a2, uint32_t a3,
                                        uint32_t b0, uint32_t b1) {
    asm volatile(
        "mma.sync.aligned.m16n8k16.row.col.f32.f16.f16.f32 "
        "{%0,%1,%2,%3}, {%4,%5,%6,%7}, {%8,%9}, {%0,%1,%2,%3};\n"
        : "+f"(c[0]), "+f"(c[1]), "+f"(c[2]), "+f"(c[3])
        : "r"(a0), "r"(a1), "r"(a2), "r"(a3), "r"(b0), "r"(b1));
}

// ---------------------------------------------------------------------------
// Pre-pass 1: x fp32 -> fp16, same layout. (destination global in-kernel)
// ---------------------------------------------------------------------------
__global__ __launch_bounds__(256) void cvt_x_kernel(const float* __restrict__ in, int n4)
{
    const int i = blockIdx.x * 256 + threadIdx.x;
    if (i < n4) {
        float4 v = ((const float4*)in)[i];
        __half2 h0 = __floats2half2_rn(v.x, v.y);
        __half2 h1 = __floats2half2_rn(v.z, v.w);
        ((__half2*)g_Xh)[2 * i + 0] = h0;
        ((__half2*)g_Xh)[2 * i + 1] = h1;
    }
}

// ---------------------------------------------------------------------------
// Pre-pass 2: transpose W [768, NDIM] fp32 -> [NDIM, 768] fp16.
// ---------------------------------------------------------------------------
template<int WHICH, int NDIM>   // WHICH: 0 -> g_WaT, 1 -> g_WpT
__global__ __launch_bounds__(256) void transpose_w_kernel(const float* __restrict__ W)
{
    __shared__ float tile[32][33];
    __half* __restrict__ out = (WHICH == 0) ? g_WaT : g_WpT;
    const int kb = blockIdx.x * 32;
    const int nb = blockIdx.y * 32;
    const int tx = threadIdx.x;    // 0..31
    const int ty = threadIdx.y;    // 0..7
#pragma unroll
    for (int r = 0; r < 32; r += 8)
        tile[ty + r][tx] = W[(size_t)(kb + ty + r) * NDIM + nb + tx];
    __syncthreads();
#pragma unroll
    for (int r = 0; r < 32; r += 8)
        out[(size_t)(nb + ty + r) * EMB + kb + tx] = __float2half_rn(tile[tx][ty + r]);
}

// ---------------------------------------------------------------------------
// fp16 double-buffered GEMM: C[M, NDIM] = A[M,768] @ B^T + bias
// A half [m][k], B half [n][k] (pre-transposed). CTA tile 128x128, BK=32
// halves (2 x k16 steps), 24 ktiles. 8 warps 4(wm)x2(wn), warp tile 32x64.
// Smem rows stride 40 halves (80B): all frag LDS.32 conflict-free.
// MODE 0: QKV -> scatter g_Q/g_K/g_V. MODE 1: proj (A = g_Yh) -> out.
// ---------------------------------------------------------------------------
#define BKH   32      // k-halves per ktile
#define HSTR  40      // smem row stride in halves (32 data + 8 pad)
#define KT16  24      // 768 / 32

template<int NDIM, int MODE>
__global__ __launch_bounds__(256, 2) void gemm_f16_kernel(
    const float* __restrict__ bias, float* __restrict__ out)
{
    __shared__ __half As[2][128 * HSTR];
    __shared__ __half Bs[2][128 * HSTR];

    const __half* __restrict__ A = (MODE == 1) ? g_Yh : g_Xh;
    const __half* __restrict__ B = (MODE == 0) ? g_WaT : g_WpT;

    const int tid = threadIdx.x;
    const int m0 = blockIdx.y * 128;
    const int n0 = blockIdx.x * 128;

    const int wid = tid >> 5;
    const int lane = tid & 31;
    const int wm = wid & 3;            // 4 warps in M (32 rows each)
    const int wn = wid >> 2;           // 2 warps in N (64 cols each)
    const int gid = lane >> 2;
    const int tig = lane & 3;

    float c[2][8][4];
#pragma unroll
    for (int mi = 0; mi < 2; mi++)
#pragma unroll
        for (int ni = 0; ni < 8; ni++)
#pragma unroll
            for (int v = 0; v < 4; v++) c[mi][ni][v] = 0.f;

    // staging: per ktile, A tile = 128 rows x 32 halves = 512 16B-chunks,
    // 2 per thread (same for B). row = idx>>2, chunk = idx&3 (8 halves).
    uint4 aReg[2], bReg[2];

    const int r0 = tid >> 2, c0 = (tid & 3);          // chunk index
    const int r1 = (tid + 256) >> 2;                   // c1 == c0

    // ---- prologue: ktile 0 -> buf 0 ----
    aReg[0] = *(const uint4*)(A + (size_t)(m0 + r0) * EMB + c0 * 8);
    aReg[1] = *(const uint4*)(A + (size_t)(m0 + r1) * EMB + c0 * 8);
    bReg[0] = *(const uint4*)(B + (size_t)(n0 + r0) * EMB + c0 * 8);
    bReg[1] = *(const uint4*)(B + (size_t)(n0 + r1) * EMB + c0 * 8);
    *(uint4*)&As[0][r0 * HSTR + c0 * 8] = aReg[0];
    *(uint4*)&As[0][r1 * HSTR + c0 * 8] = aReg[1];
    *(uint4*)&Bs[0][r0 * HSTR + c0 * 8] = bReg[0];
    *(uint4*)&Bs[0][r1 * HSTR + c0 * 8] = bReg[1];
    __syncthreads();

    for (int t = 0; t < KT16; t++) {
        const int buf = t & 1;

        // prefetch next ktile into registers
        if (t + 1 < KT16) {
            const int ks = (t + 1) * BKH;
            aReg[0] = *(const uint4*)(A + (size_t)(m0 + r0) * EMB + ks + c0 * 8);
            aReg[1] = *(const uint4*)(A + (size_t)(m0 + r1) * EMB + ks + c0 * 8);
            bReg[0] = *(const uint4*)(B + (size_t)(n0 + r0) * EMB + ks + c0 * 8);
            bReg[1] = *(const uint4*)(B + (size_t)(n0 + r1) * EMB + ks + c0 * 8);
        }

        // compute on current buffer: 2 k16 steps
        const __half* Asb = As[buf];
        const __half* Bsb = Bs[buf];
#pragma unroll
        for (int kt = 0; kt < 2; kt++) {
            const int kb = kt * 16;
            uint32_t a[2][4];
#pragma unroll
            for (int mi = 0; mi < 2; mi++) {
                const int mb = wm * 32 + mi * 16;
                a[mi][0] = *(const uint32_t*)&Asb[(mb + gid) * HSTR + kb + 2 * tig];
                a[mi][1] = *(const uint32_t*)&Asb[(mb + gid + 8) * HSTR + kb + 2 * tig];
                a[mi][2] = *(const uint32_t*)&Asb[(mb + gid) * HSTR + kb + 2 * tig + 8];
                a[mi][3] = *(const uint32_t*)&Asb[(mb + gid + 8) * HSTR + kb + 2 * tig + 8];
            }
            uint32_t b[8][2];
#pragma unroll
            for (int ni = 0; ni < 8; ni++) {
                const int nb = wn * 64 + ni * 8;
                b[ni][0] = *(const uint32_t*)&Bsb[(nb + gid) * HSTR + kb + 2 * tig];
                b[ni][1] = *(const uint32_t*)&Bsb[(nb + gid) * HSTR + kb + 2 * tig + 8];
            }
#pragma unroll
            for (int mi = 0; mi < 2; mi++)
#pragma unroll
                for (int ni = 0; ni < 8; ni++)
                    mma_f16(c[mi][ni], a[mi][0], a[mi][1], a[mi][2], a[mi][3],
                            b[ni][0], b[ni][1]);
        }

        // store prefetched ktile into other buffer
        if (t + 1 < KT16) {
            const int nb2 = buf ^ 1;
            *(uint4*)&As[nb2][r0 * HSTR + c0 * 8] = aReg[0];
            *(uint4*)&As[nb2][r1 * HSTR + c0 * 8] = aReg[1];
            *(uint4*)&Bs[nb2][r0 * HSTR + c0 * 8] = bReg[0];
            *(uint4*)&Bs[nb2][r1 * HSTR + c0 * 8] = bReg[1];
            __syncthreads();
        }
    }

    // epilogue (identical C layout to tf32 version)
#pragma unroll
    for (int mi = 0; mi < 2; mi++) {
#pragma unroll
        for (int half = 0; half < 2; half++) {
            const int m = m0 + wm * 32 + mi * 16 + gid + half * 8;
#pragma unroll
            for (int ni = 0; ni < 8; ni++) {
                const int n = n0 + wn * 64 + ni * 8 + 2 * tig;
                const float v0 = c[mi][ni][half * 2 + 0] + bias[n];
                const float v1 = c[mi][ni][half * 2 + 1] + bias[n + 1];
                if (MODE == 0) {
                    const int bb = m >> 10;
                    const int t = m & 1023;
#pragma unroll
                    for (int e = 0; e < 2; e++) {
                        const int nn = n + e;
                        const float vv = e ? v1 : v0;
                        const int which = nn / EMB;
                        const int cc = nn - which * EMB;
                        const int h = cc >> 6;
                        const int d = cc & 63;
                        float* dst = (which == 0) ? g_Q : (which == 1) ? g_K : g_V;
                        dst[(((size_t)bb * NHEAD + h) * SEQ + t) * HD + d] = vv;
                    }
                } else {
                    float2 v2; v2.x = v0; v2.y = v1;
                    *(float2*)(out + (size_t)m * NDIM + n) = v2;
                }
            }
        }
    }
}

// ---------------------------------------------------------------------------
// Tensor-core causal flash attention (tf32 m16n8k8) — unchanged except the
// final writeback stores fp16 into g_Yh for the proj GEMM.
// ---------------------------------------------------------------------------
#define ASTR 68

__global__ __launch_bounds__(128) void attn_mma_kernel()
{
    __shared__ uint32_t KVs[64 * ASTR];
    __shared__ uint32_t Ps[64 * ASTR];

    const int bh = blockIdx.y;
    const int q0 = blockIdx.x * 64;
    const int tid = threadIdx.x;
    const int wid = tid >> 5;
    const int lane = tid & 31;
    const int gid = lane >> 2;
    const int tig = lane & 3;
    const int w16 = wid * 16;

    const float* Qbase = g_Q + (size_t)bh * SEQ * HD;
    const float* Kbase = g_K + (size_t)bh * SEQ * HD;
    const float* Vbase = g_V + (size_t)bh * SEQ * HD;

#pragma unroll
    for (int i = 0; i < 8; i++) {
        int idx = tid + i * 128;
        int r = idx >> 4, dq = (idx & 15) << 2;
        float4 v = *(const float4*)(Qbase + (size_t)(q0 + r) * HD + dq);
        uint32_t* dst = &Ps[r * ASTR + dq];
        dst[0] = f2tf32(v.x * 0.125f);
        dst[1] = f2tf32(v.y * 0.125f);
        dst[2] = f2tf32(v.z * 0.125f);
        dst[3] = f2tf32(v.w * 0.125f);
    }
    __syncthreads();

    uint32_t qa[8][4];
#pragma unroll
    for (int kk = 0; kk < 8; kk++) {
        qa[kk][0] = Ps[(w16 + gid) * ASTR + 8 * kk + tig];
        qa[kk][1] = Ps[(w16 + gid + 8) * ASTR + 8 * kk + tig];
        qa[kk][2] = Ps[(w16 + gid) * ASTR + 8 * kk + tig + 4];
        qa[kk][3] = Ps[(w16 + gid + 8) * ASTR + 8 * kk + tig + 4];
    }

    float o[8][4];
#pragma unroll
    for (int ni = 0; ni < 8; ni++)
#pragma unroll
        for (int v = 0; v < 4; v++) o[ni][v] = 0.f;
    float m0 = -1e30f, m1 = -1e30f, l0 = 0.f, l1 = 0.f;

    for (int t0 = 0; t0 <= q0; t0 += 64) {
        __syncthreads();

#pragma unroll
        for (int i = 0; i < 8; i++) {
            int idx = tid + i * 128;
            int r = idx >> 4, dq = (idx & 15) << 2;
            float4 v = *(const float4*)(Kbase + (size_t)(t0 + r) * HD + dq);
            uint32_t* dst = &KVs[r * ASTR + dq];
            dst[0] = f2tf32(v.x); dst[1] = f2tf32(v.y);
            dst[2] = f2tf32(v.z); dst[3] = f2tf32(v.w);
        }
        __syncthreads();

        float4 vreg[8];
#pragma unroll
        for (int i = 0; i < 8; i++) {
            int idx = tid + i * 128;
            vreg[i] = *(const float4*)(Vbase + (size_t)(t0 + (idx >> 4)) * HD + ((idx & 15) << 2));
        }

        float s[8][4];
#pragma unroll
        for (int ni = 0; ni < 8; ni++)
#pragma unroll
            for (int v = 0; v < 4; v++) s[ni][v] = 0.f;

#pragma unroll
        for (int kk = 0; kk < 8; kk++) {
#pragma unroll
            for (int ni = 0; ni < 8; ni++) {
                uint32_t b0 = KVs[(8 * ni + gid) * ASTR + 8 * kk + tig];
                uint32_t b1 = KVs[(8 * ni + gid) * ASTR + 8 * kk + tig + 4];
                mma_tf32(s[ni], qa[kk][0], qa[kk][1], qa[kk][2], qa[kk][3], b0, b1);
            }
        }

        if (t0 == q0) {
            const int r0 = w16 + gid, r1 = r0 + 8;
#pragma unroll
            for (int ni = 0; ni < 8; ni++) {
                const int key0 = 8 * ni + 2 * tig;
                if (key0 > r0)     s[ni][0] = -1e30f;
                if (key0 + 1 > r0) s[ni][1] = -1e30f;
                if (key0 > r1)     s[ni][2] = -1e30f;
                if (key0 + 1 > r1) s[ni][3] = -1e30f;
            }
        }

        float rmax0 = -1e30f, rmax1 = -1e30f;
#pragma unroll
        for (int ni = 0; ni < 8; ni++) {
            rmax0 = fmaxf(rmax0, fmaxf(s[ni][0], s[ni][1]));
            rmax1 = fmaxf(rmax1, fmaxf(s[ni][2], s[ni][3]));
        }
        rmax0 = fmaxf(rmax0, __shfl_xor_sync(0xffffffffu, rmax0, 1));
        rmax0 = fmaxf(rmax0, __shfl_xor_sync(0xffffffffu, rmax0, 2));
        rmax1 = fmaxf(rmax1, __shfl_xor_sync(0xffffffffu, rmax1, 1));
        rmax1 = fmaxf(rmax1, __shfl_xor_sync(0xffffffffu, rmax1, 2));

        const float mn0 = fmaxf(m0, rmax0);
        const float mn1 = fmaxf(m1, rmax1);
        const float cr0 = __expf(m0 - mn0);
        const float cr1 = __expf(m1 - mn1);
        m0 = mn0; m1 = mn1;

        float sum0 = 0.f, sum1 = 0.f;
#pragma unroll
        for (int ni = 0; ni < 8; ni++) {
            s[ni][0] = __expf(s[ni][0] - m0);
            s[ni][1] = __expf(s[ni][1] - m0);
            s[ni][2] = __expf(s[ni][2] - m1);
            s[ni][3] = __expf(s[ni][3] - m1);
            sum0 += s[ni][0] + s[ni][1];
            sum1 += s[ni][2] + s[ni][3];
            o[ni][0] *= cr0; o[ni][1] *= cr0;
            o[ni][2] *= cr1; o[ni][3] *= cr1;
        }
        sum0 += __shfl_xor_sync(0xffffffffu, sum0, 1);
        sum0 += __shfl_xor_sync(0xffffffffu, sum0, 2);
        sum1 += __shfl_xor_sync(0xffffffffu, sum1, 1);
        sum1 += __shfl_xor_sync(0xffffffffu, sum1, 2);
        l0 = l0 * cr0 + sum0;
        l1 = l1 * cr1 + sum1;

        __syncthreads();

#pragma unroll
        for (int i = 0; i < 8; i++) {
            int idx = tid + i * 128;
            int r = idx >> 4, dq = (idx & 15) << 2;
            uint32_t* dst = &KVs[r * ASTR + dq];
            dst[0] = f2tf32(vreg[i].x); dst[1] = f2tf32(vreg[i].y);
            dst[2] = f2tf32(vreg[i].z); dst[3] = f2tf32(vreg[i].w);
        }
#pragma unroll
        for (int ni = 0; ni < 8; ni++) {
            uint32_t* d0 = &Ps[(w16 + gid) * ASTR + 8 * ni + 2 * tig];
            d0[0] = f2tf32(s[ni][0]); d0[1] = f2tf32(s[ni][1]);
            uint32_t* d1 = &Ps[(w16 + gid + 8) * ASTR + 8 * ni + 2 * tig];
            d1[0] = f2tf32(s[ni][2]); d1[1] = f2tf32(s[ni][3]);
        }
        __syncthreads();

#pragma unroll
        for (int kk = 0; kk < 8; kk++) {
            uint32_t pa0 = Ps[(w16 + gid) * ASTR + 8 * kk + tig];
            uint32_t pa1 = Ps[(w16 + gid + 8) * ASTR + 8 * kk + tig];
            uint32_t pa2 = Ps[(w16 + gid) * ASTR + 8 * kk + tig + 4];
            uint32_t pa3 = Ps[(w16 + gid + 8) * ASTR + 8 * kk + tig + 4];
#pragma unroll
            for (int ni = 0; ni < 8; ni++) {
                uint32_t b0 = KVs[(8 * kk + tig) * ASTR + 8 * ni + gid];
                uint32_t b1 = KVs[(8 * kk + tig + 4) * ASTR + 8 * ni + gid];
                mma_tf32(o[ni], pa0, pa1, pa2, pa3, b0, b1);
            }
        }
    }

    // writeback as fp16 into g_Yh [m][k] for the proj GEMM
    const float inv0 = 1.f / l0;
    const float inv1 = 1.f / l1;
    const int b = bh / NHEAD;
    const int h = bh - b * NHEAD;
    __half* Yb = g_Yh + ((size_t)(b * SEQ + q0 + w16 + gid)) * EMB + h * HD;
#pragma unroll
    for (int ni = 0; ni < 8; ni++) {
        *(__half2*)(Yb + 8 * ni + 2 * tig) =
            __floats2half2_rn(o[ni][0] * inv0, o[ni][1] * inv0);
        *(__half2*)(Yb + (size_t)8 * EMB + 8 * ni + 2 * tig) =
            __floats2half2_rn(o[ni][2] * inv1, o[ni][3] * inv1);
    }
}

// ---------------------------------------------------------------------------
extern "C" void kernel_launch(void* const* d_in, const int* in_sizes, int n_in,
                              void* d_out, int out_size)
{
    const float* x      = (const float*)d_in[0];
    const float* W_attn = (const float*)d_in[1];
    const float* b_attn = (const float*)d_in[2];
    const float* W_proj = (const float*)d_in[3];
    const float* b_proj = (const float*)d_in[4];
    float* out = (float*)d_out;

    (void)in_sizes; (void)n_in; (void)out_size;

    // pre-pass: fp16 conversions (destination globals selected in-kernel)
    cvt_x_kernel<<<(M_ROWS * EMB / 4 + 255) / 256, 256>>>(x, M_ROWS * EMB / 4);
    {
        dim3 b32(32, 8);
        dim3 gt1(EMB / 32, QKV_N / 32);    // (24, 72)
        transpose_w_kernel<0, QKV_N><<<gt1, b32>>>(W_attn);
        dim3 gt2(EMB / 32, EMB / 32);      // (24, 24)
        transpose_w_kernel<1, EMB><<<gt2, b32>>>(W_proj);
    }

    dim3 g1(QKV_N / 128, M_ROWS / 128);    // (18, 64)
    gemm_f16_kernel<QKV_N, 0><<<g1, 256>>>(b_attn, nullptr);

    dim3 g2(SEQ / 64, BATCH * NHEAD);      // (16, 96)
    attn_mma_kernel<<<g2, 128>>>();

    dim3 g3(EMB / 128, M_ROWS / 128);      // (6, 64)
    gemm_f16_kernel<EMB, 1><<<g3, 256>>>(b_proj, out);
}

// round 15
// speedup vs baseline: 1.7649x; 1.2299x over previous
#include <cuda_runtime.h>
#include <cuda_fp16.h>
#include <math.h>
#include <stdint.h>

// Problem constants
#define BATCH 8
#define SEQ   1024
#define EMB   768
#define NHEAD 12
#define HD    64
#define M_ROWS (BATCH * SEQ)        // 8192
#define QKV_N  (3 * EMB)            // 2304

// Scratch (device globals — no allocations allowed)
__device__ __half g_Qh[BATCH * NHEAD * SEQ * HD];  // [b,h,t,d] fp16
__device__ __half g_Kh[BATCH * NHEAD * SEQ * HD];
__device__ __half g_Vh[BATCH * NHEAD * SEQ * HD];
__device__ __half g_Xh[M_ROWS * EMB];              // x as fp16, [m][k]
__device__ __half g_WaT[QKV_N * EMB];              // W_attn^T fp16, [n][k]
__device__ __half g_WpT[EMB * EMB];                // W_proj^T fp16, [n][k]
__device__ __half g_Yh[M_ROWS * EMB];              // attention out fp16, [m][k]

// ---------------------------------------------------------------------------
// helpers
// ---------------------------------------------------------------------------
__device__ __forceinline__ void mma_f16(float c[4],
                                        uint32_t a0, uint32_t a1, uint32_t a2, uint32_t a3,
                                        uint32_t b0, uint32_t b1) {
    asm volatile(
        "mma.sync.aligned.m16n8k16.row.col.f32.f16.f16.f32 "
        "{%0,%1,%2,%3}, {%4,%5,%6,%7}, {%8,%9}, {%0,%1,%2,%3};\n"
        : "+f"(c[0]), "+f"(c[1]), "+f"(c[2]), "+f"(c[3])
        : "r"(a0), "r"(a1), "r"(a2), "r"(a3), "r"(b0), "r"(b1));
}

// ---------------------------------------------------------------------------
// Pre-pass 1: x fp32 -> fp16, same layout.
// ---------------------------------------------------------------------------
__global__ __launch_bounds__(256) void cvt_x_kernel(const float* __restrict__ in, int n4)
{
    const int i = blockIdx.x * 256 + threadIdx.x;
    if (i < n4) {
        float4 v = ((const float4*)in)[i];
        ((__half2*)g_Xh)[2 * i + 0] = __floats2half2_rn(v.x, v.y);
        ((__half2*)g_Xh)[2 * i + 1] = __floats2half2_rn(v.z, v.w);
    }
}

// ---------------------------------------------------------------------------
// Pre-pass 2: transpose W [768, NDIM] fp32 -> [NDIM, 768] fp16.
// ---------------------------------------------------------------------------
template<int WHICH, int NDIM>   // WHICH: 0 -> g_WaT, 1 -> g_WpT
__global__ __launch_bounds__(256) void transpose_w_kernel(const float* __restrict__ W)
{
    __shared__ float tile[32][33];
    __half* __restrict__ out = (WHICH == 0) ? g_WaT : g_WpT;
    const int kb = blockIdx.x * 32;
    const int nb = blockIdx.y * 32;
    const int tx = threadIdx.x;
    const int ty = threadIdx.y;
#pragma unroll
    for (int r = 0; r < 32; r += 8)
        tile[ty + r][tx] = W[(size_t)(kb + ty + r) * NDIM + nb + tx];
    __syncthreads();
#pragma unroll
    for (int r = 0; r < 32; r += 8)
        out[(size_t)(nb + ty + r) * EMB + kb + tx] = __float2half_rn(tile[tx][ty + r]);
}

// ---------------------------------------------------------------------------
// fp16 double-buffered GEMM (unchanged from R13 except MODE 0 writes fp16
// Q/K/V): C[M, NDIM] = A[M,768] @ B^T + bias. CTA 128x128, BK=32 halves.
// ---------------------------------------------------------------------------
#define BKH   32
#define HSTR  40
#define KT16  24

template<int NDIM, int MODE>
__global__ __launch_bounds__(256, 2) void gemm_f16_kernel(
    const float* __restrict__ bias, float* __restrict__ out)
{
    __shared__ __half As[2][128 * HSTR];
    __shared__ __half Bs[2][128 * HSTR];

    const __half* __restrict__ A = (MODE == 1) ? g_Yh : g_Xh;
    const __half* __restrict__ B = (MODE == 0) ? g_WaT : g_WpT;

    const int tid = threadIdx.x;
    const int m0 = blockIdx.y * 128;
    const int n0 = blockIdx.x * 128;

    const int wid = tid >> 5;
    const int lane = tid & 31;
    const int wm = wid & 3;
    const int wn = wid >> 2;
    const int gid = lane >> 2;
    const int tig = lane & 3;

    float c[2][8][4];
#pragma unroll
    for (int mi = 0; mi < 2; mi++)
#pragma unroll
        for (int ni = 0; ni < 8; ni++)
#pragma unroll
            for (int v = 0; v < 4; v++) c[mi][ni][v] = 0.f;

    uint4 aReg[2], bReg[2];
    const int r0 = tid >> 2, c0 = (tid & 3);
    const int r1 = (tid + 256) >> 2;

    aReg[0] = *(const uint4*)(A + (size_t)(m0 + r0) * EMB + c0 * 8);
    aReg[1] = *(const uint4*)(A + (size_t)(m0 + r1) * EMB + c0 * 8);
    bReg[0] = *(const uint4*)(B + (size_t)(n0 + r0) * EMB + c0 * 8);
    bReg[1] = *(const uint4*)(B + (size_t)(n0 + r1) * EMB + c0 * 8);
    *(uint4*)&As[0][r0 * HSTR + c0 * 8] = aReg[0];
    *(uint4*)&As[0][r1 * HSTR + c0 * 8] = aReg[1];
    *(uint4*)&Bs[0][r0 * HSTR + c0 * 8] = bReg[0];
    *(uint4*)&Bs[0][r1 * HSTR + c0 * 8] = bReg[1];
    __syncthreads();

    for (int t = 0; t < KT16; t++) {
        const int buf = t & 1;

        if (t + 1 < KT16) {
            const int ks = (t + 1) * BKH;
            aReg[0] = *(const uint4*)(A + (size_t)(m0 + r0) * EMB + ks + c0 * 8);
            aReg[1] = *(const uint4*)(A + (size_t)(m0 + r1) * EMB + ks + c0 * 8);
            bReg[0] = *(const uint4*)(B + (size_t)(n0 + r0) * EMB + ks + c0 * 8);
            bReg[1] = *(const uint4*)(B + (size_t)(n0 + r1) * EMB + ks + c0 * 8);
        }

        const __half* Asb = As[buf];
        const __half* Bsb = Bs[buf];
#pragma unroll
        for (int kt = 0; kt < 2; kt++) {
            const int kb = kt * 16;
            uint32_t a[2][4];
#pragma unroll
            for (int mi = 0; mi < 2; mi++) {
                const int mb = wm * 32 + mi * 16;
                a[mi][0] = *(const uint32_t*)&Asb[(mb + gid) * HSTR + kb + 2 * tig];
                a[mi][1] = *(const uint32_t*)&Asb[(mb + gid + 8) * HSTR + kb + 2 * tig];
                a[mi][2] = *(const uint32_t*)&Asb[(mb + gid) * HSTR + kb + 2 * tig + 8];
                a[mi][3] = *(const uint32_t*)&Asb[(mb + gid + 8) * HSTR + kb + 2 * tig + 8];
            }
            uint32_t b[8][2];
#pragma unroll
            for (int ni = 0; ni < 8; ni++) {
                const int nb = wn * 64 + ni * 8;
                b[ni][0] = *(const uint32_t*)&Bsb[(nb + gid) * HSTR + kb + 2 * tig];
                b[ni][1] = *(const uint32_t*)&Bsb[(nb + gid) * HSTR + kb + 2 * tig + 8];
            }
#pragma unroll
            for (int mi = 0; mi < 2; mi++)
#pragma unroll
                for (int ni = 0; ni < 8; ni++)
                    mma_f16(c[mi][ni], a[mi][0], a[mi][1], a[mi][2], a[mi][3],
                            b[ni][0], b[ni][1]);
        }

        if (t + 1 < KT16) {
            const int nb2 = buf ^ 1;
            *(uint4*)&As[nb2][r0 * HSTR + c0 * 8] = aReg[0];
            *(uint4*)&As[nb2][r1 * HSTR + c0 * 8] = aReg[1];
            *(uint4*)&Bs[nb2][r0 * HSTR + c0 * 8] = bReg[0];
            *(uint4*)&Bs[nb2][r1 * HSTR + c0 * 8] = bReg[1];
            __syncthreads();
        }
    }

    // epilogue
#pragma unroll
    for (int mi = 0; mi < 2; mi++) {
#pragma unroll
        for (int half = 0; half < 2; half++) {
            const int m = m0 + wm * 32 + mi * 16 + gid + half * 8;
#pragma unroll
            for (int ni = 0; ni < 8; ni++) {
                const int n = n0 + wn * 64 + ni * 8 + 2 * tig;
                const float v0 = c[mi][ni][half * 2 + 0] + bias[n];
                const float v1 = c[mi][ni][half * 2 + 1] + bias[n + 1];
                if (MODE == 0) {
                    // write fp16 Q/K/V [b,h,t,d]; (n, n+1) stay within one head
                    const int bb = m >> 10;
                    const int t = m & 1023;
                    const int which = n / EMB;
                    const int cc = n - which * EMB;
                    const int h = cc >> 6;
                    const int d = cc & 63;
                    __half* dst = (which == 0) ? g_Qh : (which == 1) ? g_Kh : g_Vh;
                    *(__half2*)(dst + (((size_t)bb * NHEAD + h) * SEQ + t) * HD + d) =
                        __floats2half2_rn(v0, v1);
                } else {
                    float2 v2; v2.x = v0; v2.y = v1;
                    *(float2*)(out + (size_t)m * NDIM + n) = v2;
                }
            }
        }
    }
}

// ---------------------------------------------------------------------------
// fp16 tensor-core causal flash attention (m16n8k16).
// 4 warps, 64 q-rows (16/warp), 64-key tiles. K tile [key][d]; V staged
// TRANSPOSED [d][key] for packed B-frags; P through smem as fp16.
// ---------------------------------------------------------------------------
#define FSTR 72   // halves per smem row (64 + 8)

__global__ __launch_bounds__(128) void attn_f16_kernel()
{
    __shared__ __half KVs[64 * FSTR];   // K tile, then V^T tile
    __shared__ __half Ps[64 * FSTR];    // Q tile, then P tile

    const int bh = blockIdx.y;
    const int q0 = blockIdx.x * 64;
    const int tid = threadIdx.x;
    const int wid = tid >> 5;
    const int lane = tid & 31;
    const int gid = lane >> 2;
    const int tig = lane & 3;
    const int w16 = wid * 16;

    const __half* Qbase = g_Qh + (size_t)bh * SEQ * HD;
    const __half* Kbase = g_Kh + (size_t)bh * SEQ * HD;
    const __half* Vbase = g_Vh + (size_t)bh * SEQ * HD;

    // ---- stage Q tile [row][d] (512 uint4, 4/thread) ----
#pragma unroll
    for (int i = 0; i < 4; i++) {
        const int idx = tid + i * 128;
        const int r = idx >> 3, c8 = idx & 7;
        *(uint4*)&Ps[r * FSTR + c8 * 8] =
            *(const uint4*)(Qbase + (size_t)(q0 + r) * HD + c8 * 8);
    }
    __syncthreads();

    // Q A-fragments (4 k16 steps over d=64)
    uint32_t qa[4][4];
#pragma unroll
    for (int kk = 0; kk < 4; kk++) {
        const int kb = 16 * kk;
        qa[kk][0] = *(const uint32_t*)&Ps[(w16 + gid) * FSTR + kb + 2 * tig];
        qa[kk][1] = *(const uint32_t*)&Ps[(w16 + gid + 8) * FSTR + kb + 2 * tig];
        qa[kk][2] = *(const uint32_t*)&Ps[(w16 + gid) * FSTR + kb + 2 * tig + 8];
        qa[kk][3] = *(const uint32_t*)&Ps[(w16 + gid + 8) * FSTR + kb + 2 * tig + 8];
    }

    float o[8][4];
#pragma unroll
    for (int ni = 0; ni < 8; ni++)
#pragma unroll
        for (int v = 0; v < 4; v++) o[ni][v] = 0.f;
    float m0 = -1e30f, m1 = -1e30f, l0 = 0.f, l1 = 0.f;

    for (int t0 = 0; t0 <= q0; t0 += 64) {
        __syncthreads();   // prev-iter PV reads of KVs/Ps done

        // ---- stage K tile [key][d] ----
#pragma unroll
        for (int i = 0; i < 4; i++) {
            const int idx = tid + i * 128;
            const int r = idx >> 3, c8 = idx & 7;
            *(uint4*)&KVs[r * FSTR + c8 * 8] =
                *(const uint4*)(Kbase + (size_t)(t0 + r) * HD + c8 * 8);
        }
        __syncthreads();

        // ---- V loads early (keys 2*lane, 2*lane+1; d-range wid*16..+15) ----
        uint4 v0a = *(const uint4*)(Vbase + (size_t)(t0 + 2 * lane) * HD + w16);
        uint4 v0b = *(const uint4*)(Vbase + (size_t)(t0 + 2 * lane) * HD + w16 + 8);
        uint4 v1a = *(const uint4*)(Vbase + (size_t)(t0 + 2 * lane + 1) * HD + w16);
        uint4 v1b = *(const uint4*)(Vbase + (size_t)(t0 + 2 * lane + 1) * HD + w16 + 8);

        // ---- S = Q @ K^T ----
        float s[8][4];
#pragma unroll
        for (int ni = 0; ni < 8; ni++)
#pragma unroll
            for (int v = 0; v < 4; v++) s[ni][v] = 0.f;
#pragma unroll
        for (int kk = 0; kk < 4; kk++) {
            const int kb = 16 * kk;
#pragma unroll
            for (int ni = 0; ni < 8; ni++) {
                uint32_t b0 = *(const uint32_t*)&KVs[(8 * ni + gid) * FSTR + kb + 2 * tig];
                uint32_t b1 = *(const uint32_t*)&KVs[(8 * ni + gid) * FSTR + kb + 2 * tig + 8];
                mma_f16(s[ni], qa[kk][0], qa[kk][1], qa[kk][2], qa[kk][3], b0, b1);
            }
        }
#pragma unroll
        for (int ni = 0; ni < 8; ni++)
#pragma unroll
            for (int v = 0; v < 4; v++) s[ni][v] *= 0.125f;

        // ---- causal mask (diagonal tile) ----
        if (t0 == q0) {
            const int r0 = w16 + gid, r1 = r0 + 8;
#pragma unroll
            for (int ni = 0; ni < 8; ni++) {
                const int key0 = 8 * ni + 2 * tig;
                if (key0 > r0)     s[ni][0] = -1e30f;
                if (key0 + 1 > r0) s[ni][1] = -1e30f;
                if (key0 > r1)     s[ni][2] = -1e30f;
                if (key0 + 1 > r1) s[ni][3] = -1e30f;
            }
        }

        // ---- online softmax ----
        float rmax0 = -1e30f, rmax1 = -1e30f;
#pragma unroll
        for (int ni = 0; ni < 8; ni++) {
            rmax0 = fmaxf(rmax0, fmaxf(s[ni][0], s[ni][1]));
            rmax1 = fmaxf(rmax1, fmaxf(s[ni][2], s[ni][3]));
        }
        rmax0 = fmaxf(rmax0, __shfl_xor_sync(0xffffffffu, rmax0, 1));
        rmax0 = fmaxf(rmax0, __shfl_xor_sync(0xffffffffu, rmax0, 2));
        rmax1 = fmaxf(rmax1, __shfl_xor_sync(0xffffffffu, rmax1, 1));
        rmax1 = fmaxf(rmax1, __shfl_xor_sync(0xffffffffu, rmax1, 2));

        const float mn0 = fmaxf(m0, rmax0);
        const float mn1 = fmaxf(m1, rmax1);
        const float cr0 = __expf(m0 - mn0);
        const float cr1 = __expf(m1 - mn1);
        m0 = mn0; m1 = mn1;

        float sum0 = 0.f, sum1 = 0.f;
#pragma unroll
        for (int ni = 0; ni < 8; ni++) {
            s[ni][0] = __expf(s[ni][0] - m0);
            s[ni][1] = __expf(s[ni][1] - m0);
            s[ni][2] = __expf(s[ni][2] - m1);
            s[ni][3] = __expf(s[ni][3] - m1);
            sum0 += s[ni][0] + s[ni][1];
            sum1 += s[ni][2] + s[ni][3];
            o[ni][0] *= cr0; o[ni][1] *= cr0;
            o[ni][2] *= cr1; o[ni][3] *= cr1;
        }
        sum0 += __shfl_xor_sync(0xffffffffu, sum0, 1);
        sum0 += __shfl_xor_sync(0xffffffffu, sum0, 2);
        sum1 += __shfl_xor_sync(0xffffffffu, sum1, 1);
        sum1 += __shfl_xor_sync(0xffffffffu, sum1, 2);
        l0 = l0 * cr0 + sum0;
        l1 = l1 * cr1 + sum1;

        __syncthreads();   // all warps done reading K tile

        // ---- stage V^T [d][key] (half2 per d-row, CF: word = d*36 + lane) ----
        {
            const __half* h0a = (const __half*)&v0a;
            const __half* h1a = (const __half*)&v1a;
            const __half* h0b = (const __half*)&v0b;
            const __half* h1b = (const __half*)&v1b;
#pragma unroll
            for (int j = 0; j < 8; j++) {
                *(__half2*)&KVs[(w16 + j) * FSTR + 2 * lane] =
                    __halves2half2(h0a[j], h1a[j]);
                *(__half2*)&KVs[(w16 + 8 + j) * FSTR + 2 * lane] =
                    __halves2half2(h0b[j], h1b[j]);
            }
        }
        // ---- stage P tile [row][key] as fp16 ----
#pragma unroll
        for (int ni = 0; ni < 8; ni++) {
            *(__half2*)&Ps[(w16 + gid) * FSTR + 8 * ni + 2 * tig] =
                __floats2half2_rn(s[ni][0], s[ni][1]);
            *(__half2*)&Ps[(w16 + gid + 8) * FSTR + 8 * ni + 2 * tig] =
                __floats2half2_rn(s[ni][2], s[ni][3]);
        }
        __syncthreads();

        // ---- O += P @ V ----
#pragma unroll
        for (int kk = 0; kk < 4; kk++) {
            const int kb = 16 * kk;
            uint32_t pa0 = *(const uint32_t*)&Ps[(w16 + gid) * FSTR + kb + 2 * tig];
            uint32_t pa1 = *(const uint32_t*)&Ps[(w16 + gid + 8) * FSTR + kb + 2 * tig];
            uint32_t pa2 = *(const uint32_t*)&Ps[(w16 + gid) * FSTR + kb + 2 * tig + 8];
            uint32_t pa3 = *(const uint32_t*)&Ps[(w16 + gid + 8) * FSTR + kb + 2 * tig + 8];
#pragma unroll
            for (int ni = 0; ni < 8; ni++) {
                uint32_t b0 = *(const uint32_t*)&KVs[(8 * ni + gid) * FSTR + kb + 2 * tig];
                uint32_t b1 = *(const uint32_t*)&KVs[(8 * ni + gid) * FSTR + kb + 2 * tig + 8];
                mma_f16(o[ni], pa0, pa1, pa2, pa3, b0, b1);
            }
        }
    }

    // ---- writeback fp16 into g_Yh [m][k] for the proj GEMM ----
    const float inv0 = 1.f / l0;
    const float inv1 = 1.f / l1;
    const int b = bh / NHEAD;
    const int h = bh - b * NHEAD;
    __half* Yb = g_Yh + ((size_t)(b * SEQ + q0 + w16 + gid)) * EMB + h * HD;
#pragma unroll
    for (int ni = 0; ni < 8; ni++) {
        *(__half2*)(Yb + 8 * ni + 2 * tig) =
            __floats2half2_rn(o[ni][0] * inv0, o[ni][1] * inv0);
        *(__half2*)(Yb + (size_t)8 * EMB + 8 * ni + 2 * tig) =
            __floats2half2_rn(o[ni][2] * inv1, o[ni][3] * inv1);
    }
}

// ---------------------------------------------------------------------------
extern "C" void kernel_launch(void* const* d_in, const int* in_sizes, int n_in,
                              void* d_out, int out_size)
{
    const float* x      = (const float*)d_in[0];
    const float* W_attn = (const float*)d_in[1];
    const float* b_attn = (const float*)d_in[2];
    const float* W_proj = (const float*)d_in[3];
    const float* b_proj = (const float*)d_in[4];
    float* out = (float*)d_out;

    (void)in_sizes; (void)n_in; (void)out_size;

    // pre-pass: fp16 conversions
    cvt_x_kernel<<<(M_ROWS * EMB / 4 + 255) / 256, 256>>>(x, M_ROWS * EMB / 4);
    {
        dim3 b32(32, 8);
        dim3 gt1(EMB / 32, QKV_N / 32);    // (24, 72)
        transpose_w_kernel<0, QKV_N><<<gt1, b32>>>(W_attn);
        dim3 gt2(EMB / 32, EMB / 32);      // (24, 24)
        transpose_w_kernel<1, EMB><<<gt2, b32>>>(W_proj);
    }

    dim3 g1(QKV_N / 128, M_ROWS / 128);    // (18, 64)
    gemm_f16_kernel<QKV_N, 0><<<g1, 256>>>(b_attn, nullptr);

    dim3 g2(SEQ / 64, BATCH * NHEAD);      // (16, 96)
    attn_f16_kernel<<<g2, 128>>>();

    dim3 g3(EMB / 128, M_ROWS / 128);      // (6, 64)
    gemm_f16_kernel<EMB, 1><<<g3, 256>>>(b_proj, out);
}